// round 13
// baseline (speedup 1.0000x reference)
#include <cuda_runtime.h>
#include <cuda_fp16.h>
#include <cfloat>

#define BB 4
#define CC 64
#define NN 65536
#define KK 16
#define TILE_N 64

// 33.5 MB transposed fp16 features: [B][N][C]
__device__ __align__(16) __half g_ft[(size_t)BB * NN * CC];

// ---------------------------------------------------------------------------
// Kernel 1: transpose + convert a 2-batch chunk: [C][N] f32 -> g_ft [N][C] f16
// blockIdx.z = batch within chunk. R8-proven body.
// ---------------------------------------------------------------------------
__global__ __launch_bounds__(256) void transpose_kernel(const float* __restrict__ f,
                                                        int b0) {
    __shared__ float tile[64][68];
    int b  = b0 + blockIdx.z;
    int n0 = blockIdx.x * 64;
    int tid = threadIdx.x;

    int rx = tid & 15;
    int ry = tid >> 4;
    const float4* src = (const float4*)(f + (size_t)b * CC * NN + n0);
#pragma unroll
    for (int j = 0; j < 4; j++) {
        int c = ry + 16 * j;
        float4 v = __ldcs(&src[(size_t)c * (NN / 4) + rx]);
        *(float4*)&tile[c][rx * 4] = v;   // 272B row stride: 16B-aligned
    }
    __syncthreads();

    int tx = tid & 7;
    int ty = tid >> 3;
    __half* dst = g_ft + ((size_t)b * NN + n0) * CC;
#pragma unroll
    for (int j = 0; j < 2; j++) {
        int n = ty + 32 * j;
        int c = tx * 8;
        uint4 hv;
        __half2* h = (__half2*)&hv;
#pragma unroll
        for (int t = 0; t < 4; t++) {
            int p = (t + tx) & 3;       // rotated pair: packed F2FP, low conflicts
            h[p] = __floats2half2_rn(tile[c + 2 * p][n], tile[c + 2 * p + 1][n]);
        }
        *(uint4*)&dst[(size_t)n * CC + c] = hv;
    }
}

// ---------------------------------------------------------------------------
// Kernel 2: gather + max for a 2-batch chunk (exact R8 body, best 46.4us/4B).
// blockIdx.y = batch within chunk.
// ---------------------------------------------------------------------------
__global__ __launch_bounds__(256) void gather_max_kernel(
    const int* __restrict__ nb, float* __restrict__ out, int b0)
{
    __shared__ int   s_idx[KK][TILE_N];
    __shared__ float s_out[CC][TILE_N + 1];

    int b  = b0 + blockIdx.y;
    int n0 = blockIdx.x * TILE_N;
    int tid = threadIdx.x;

    const int* nbp = nb + (size_t)b * KK * NN + n0;
    for (int i = tid; i < KK * TILE_N; i += 256) {
        int k = i >> 6;
        int j = i & (TILE_N - 1);
        s_idx[k][j] = nbp[(size_t)k * NN + j];
    }
    __syncthreads();

    int warp = tid >> 5;
    int lane = tid & 31;
    int q    = lane >> 3;
    int cg   = lane & 7;

    const uint4* ftb = (const uint4*)(g_ft + (size_t)b * NN * CC);

    int colA = warp * 8 + q;
    int colB = colA + 4;

    const __half2 ninf2 = __halves2half2(__ushort_as_half(0xFC00),
                                         __ushort_as_half(0xFC00));
    __half2 accA[4] = {ninf2, ninf2, ninf2, ninf2};
    __half2 accB[4] = {ninf2, ninf2, ninf2, ninf2};

#pragma unroll
    for (int k = 0; k < KK; k++) {
        int idxA = s_idx[k][colA];
        int idxB = s_idx[k][colB];
        uint4 ra = __ldg(&ftb[(size_t)idxA * (CC / 8) + cg]);
        uint4 rb = __ldg(&ftb[(size_t)idxB * (CC / 8) + cg]);
        const __half2* va = (const __half2*)&ra;
        const __half2* vb = (const __half2*)&rb;
#pragma unroll
        for (int t = 0; t < 4; t++) {
            accA[t] = __hmax2(accA[t], va[t]);
            accB[t] = __hmax2(accB[t], vb[t]);
        }
    }

    int c = cg * 8;
#pragma unroll
    for (int t = 0; t < 4; t++) {
        float2 fa = __half22float2(accA[t]);
        float2 fb = __half22float2(accB[t]);
        s_out[c + 2 * t + 0][colA] = fa.x;
        s_out[c + 2 * t + 1][colA] = fa.y;
        s_out[c + 2 * t + 0][colB] = fb.x;
        s_out[c + 2 * t + 1][colB] = fb.y;
    }
    __syncthreads();

    float* outp = out + (size_t)b * CC * NN + n0;
    for (int i = tid; i < CC * TILE_N; i += 256) {
        int cc = i >> 6;
        int j  = i & 63;
        __stcs(&outp[(size_t)cc * NN + j], s_out[cc][j]);
    }
}

// ---------------------------------------------------------------------------
// Pipeline: 2 chunks of 2 batches. ALL kernels run on private non-blocking
// streams (nothing on stream 0 — legacy-stream semantics would serialize
// against every other stream, which matches R11's flat timeline). Stream 0
// carries only the fork/join events.
// ---------------------------------------------------------------------------
extern "C" void kernel_launch(void* const* d_in, const int* in_sizes, int n_in,
                              void* d_out, int out_size)
{
    const float* features     = (const float*)d_in[0];
    const int*   neighborhood = (const int*)d_in[1];
    float*       out          = (float*)d_out;

    static cudaStream_t s1 = nullptr, s2 = nullptr;
    static cudaEvent_t  eFork, eT[2], eDone;
    if (!s1) {
        cudaStreamCreateWithFlags(&s1, cudaStreamNonBlocking);
        cudaStreamCreateWithFlags(&s2, cudaStreamNonBlocking);
        cudaEventCreateWithFlags(&eFork, cudaEventDisableTiming);
        cudaEventCreateWithFlags(&eT[0], cudaEventDisableTiming);
        cudaEventCreateWithFlags(&eT[1], cudaEventDisableTiming);
        cudaEventCreateWithFlags(&eDone, cudaEventDisableTiming);
    }

    // Fork both worker streams off the launch/capture stream.
    cudaEventRecord(eFork, 0);
    cudaStreamWaitEvent(s1, eFork, 0);
    cudaStreamWaitEvent(s2, eFork, 0);

    dim3 tgrid(NN / 64, 1, 2);       // 2048 blocks per chunk
    dim3 ggrid(NN / TILE_N, 2);      // 2048 blocks per chunk

    for (int chunk = 0; chunk < 2; chunk++) {
        transpose_kernel<<<tgrid, 256, 0, s1>>>(features, chunk * 2);
        cudaEventRecord(eT[chunk], s1);
    }
    for (int chunk = 0; chunk < 2; chunk++) {
        cudaStreamWaitEvent(s2, eT[chunk], 0);
        gather_max_kernel<<<ggrid, 256, 0, s2>>>(neighborhood, out, chunk * 2);
    }

    // Join back to the launch/capture stream.
    cudaEventRecord(eDone, s2);
    cudaStreamWaitEvent(0, eDone, 0);
}

// round 14
// speedup vs baseline: 1.0005x; 1.0005x over previous
#include <cuda_runtime.h>
#include <cuda_fp16.h>
#include <cfloat>

#define BB 4
#define CC 64
#define NN 65536
#define KK 16
#define TILE_N 64

// 33.5 MB transposed fp16 features: [B][N][C]
__device__ __align__(16) __half g_ft[(size_t)BB * NN * CC];

// ---------------------------------------------------------------------------
// Kernel 1: transpose + convert a 2-batch chunk: [C][N] f32 -> g_ft [N][C] f16
// blockIdx.z = batch within chunk. R8-proven body.
// ---------------------------------------------------------------------------
__global__ __launch_bounds__(256) void transpose_kernel(const float* __restrict__ f,
                                                        int b0) {
    __shared__ float tile[64][68];
    int b  = b0 + blockIdx.z;
    int n0 = blockIdx.x * 64;
    int tid = threadIdx.x;

    int rx = tid & 15;
    int ry = tid >> 4;
    const float4* src = (const float4*)(f + (size_t)b * CC * NN + n0);
#pragma unroll
    for (int j = 0; j < 4; j++) {
        int c = ry + 16 * j;
        float4 v = __ldcs(&src[(size_t)c * (NN / 4) + rx]);
        *(float4*)&tile[c][rx * 4] = v;   // 272B row stride: 16B-aligned
    }
    __syncthreads();

    int tx = tid & 7;
    int ty = tid >> 3;
    __half* dst = g_ft + ((size_t)b * NN + n0) * CC;
#pragma unroll
    for (int j = 0; j < 2; j++) {
        int n = ty + 32 * j;
        int c = tx * 8;
        uint4 hv;
        __half2* h = (__half2*)&hv;
#pragma unroll
        for (int t = 0; t < 4; t++) {
            int p = (t + tx) & 3;       // rotated pair: packed F2FP, low conflicts
            h[p] = __floats2half2_rn(tile[c + 2 * p][n], tile[c + 2 * p + 1][n]);
        }
        *(uint4*)&dst[(size_t)n * CC + c] = hv;
    }
}

// ---------------------------------------------------------------------------
// Kernel 2: gather + max for a 2-batch chunk (exact R8 body, best 46.4us/4B).
// blockIdx.y = batch within chunk.
// ---------------------------------------------------------------------------
__global__ __launch_bounds__(256) void gather_max_kernel(
    const int* __restrict__ nb, float* __restrict__ out, int b0)
{
    __shared__ int   s_idx[KK][TILE_N];
    __shared__ float s_out[CC][TILE_N + 1];

    int b  = b0 + blockIdx.y;
    int n0 = blockIdx.x * TILE_N;
    int tid = threadIdx.x;

    const int* nbp = nb + (size_t)b * KK * NN + n0;
    for (int i = tid; i < KK * TILE_N; i += 256) {
        int k = i >> 6;
        int j = i & (TILE_N - 1);
        s_idx[k][j] = nbp[(size_t)k * NN + j];
    }
    __syncthreads();

    int warp = tid >> 5;
    int lane = tid & 31;
    int q    = lane >> 3;
    int cg   = lane & 7;

    const uint4* ftb = (const uint4*)(g_ft + (size_t)b * NN * CC);

    int colA = warp * 8 + q;
    int colB = colA + 4;

    const __half2 ninf2 = __halves2half2(__ushort_as_half(0xFC00),
                                         __ushort_as_half(0xFC00));
    __half2 accA[4] = {ninf2, ninf2, ninf2, ninf2};
    __half2 accB[4] = {ninf2, ninf2, ninf2, ninf2};

#pragma unroll
    for (int k = 0; k < KK; k++) {
        int idxA = s_idx[k][colA];
        int idxB = s_idx[k][colB];
        uint4 ra = __ldg(&ftb[(size_t)idxA * (CC / 8) + cg]);
        uint4 rb = __ldg(&ftb[(size_t)idxB * (CC / 8) + cg]);
        const __half2* va = (const __half2*)&ra;
        const __half2* vb = (const __half2*)&rb;
#pragma unroll
        for (int t = 0; t < 4; t++) {
            accA[t] = __hmax2(accA[t], va[t]);
            accB[t] = __hmax2(accB[t], vb[t]);
        }
    }

    int c = cg * 8;
#pragma unroll
    for (int t = 0; t < 4; t++) {
        float2 fa = __half22float2(accA[t]);
        float2 fb = __half22float2(accB[t]);
        s_out[c + 2 * t + 0][colA] = fa.x;
        s_out[c + 2 * t + 1][colA] = fa.y;
        s_out[c + 2 * t + 0][colB] = fb.x;
        s_out[c + 2 * t + 1][colB] = fb.y;
    }
    __syncthreads();

    float* outp = out + (size_t)b * CC * NN + n0;
    for (int i = tid; i < CC * TILE_N; i += 256) {
        int cc = i >> 6;
        int j  = i & 63;
        __stcs(&outp[(size_t)cc * NN + j], s_out[cc][j]);
    }
}

// ---------------------------------------------------------------------------
// Pipeline: 2 chunks of 2 batches. ALL kernels run on private non-blocking
// streams (nothing on stream 0 — legacy-stream semantics would serialize
// against every other stream, which matches R11's flat timeline). Stream 0
// carries only the fork/join events.
// ---------------------------------------------------------------------------
extern "C" void kernel_launch(void* const* d_in, const int* in_sizes, int n_in,
                              void* d_out, int out_size)
{
    const float* features     = (const float*)d_in[0];
    const int*   neighborhood = (const int*)d_in[1];
    float*       out          = (float*)d_out;

    static cudaStream_t s1 = nullptr, s2 = nullptr;
    static cudaEvent_t  eFork, eT[2], eDone;
    if (!s1) {
        cudaStreamCreateWithFlags(&s1, cudaStreamNonBlocking);
        cudaStreamCreateWithFlags(&s2, cudaStreamNonBlocking);
        cudaEventCreateWithFlags(&eFork, cudaEventDisableTiming);
        cudaEventCreateWithFlags(&eT[0], cudaEventDisableTiming);
        cudaEventCreateWithFlags(&eT[1], cudaEventDisableTiming);
        cudaEventCreateWithFlags(&eDone, cudaEventDisableTiming);
    }

    // Fork both worker streams off the launch/capture stream.
    cudaEventRecord(eFork, 0);
    cudaStreamWaitEvent(s1, eFork, 0);
    cudaStreamWaitEvent(s2, eFork, 0);

    dim3 tgrid(NN / 64, 1, 2);       // 2048 blocks per chunk
    dim3 ggrid(NN / TILE_N, 2);      // 2048 blocks per chunk

    for (int chunk = 0; chunk < 2; chunk++) {
        transpose_kernel<<<tgrid, 256, 0, s1>>>(features, chunk * 2);
        cudaEventRecord(eT[chunk], s1);
    }
    for (int chunk = 0; chunk < 2; chunk++) {
        cudaStreamWaitEvent(s2, eT[chunk], 0);
        gather_max_kernel<<<ggrid, 256, 0, s2>>>(neighborhood, out, chunk * 2);
    }

    // Join back to the launch/capture stream.
    cudaEventRecord(eDone, s2);
    cudaStreamWaitEvent(0, eDone, 0);
}